// round 4
// baseline (speedup 1.0000x reference)
#include <cuda_runtime.h>

#define H_IMG 200
#define W_IMG 200
#define VOLN  256
#define SUBS  32   // full warp cooperates on ONE pixel, 32 consecutive samples

__global__ void __launch_bounds__(256) drr_kernel(
    const float* __restrict__ vol,
    const float* __restrict__ k_inv,    // (1,3,3)
    const float* __restrict__ rt_inv,   // (1,4,4)
    const float* __restrict__ sdd_p,    // (1,)
    const float* __restrict__ aff,      // (4,4)
    const int*   __restrict__ ns_p,     // scalar
    float* __restrict__ out)            // (H*W,)
{
    int gtid = blockIdx.x * blockDim.x + threadIdx.x;
    int pix  = gtid >> 5;            // / 32
    int sub  = gtid & 31;
    if (pix >= H_IMG * W_IMG) return;

    int u = pix % W_IMG;
    int v = pix / W_IMG;

    float sdd = sdd_p[0];
    int   ns  = ns_p[0];
    float nm1 = (float)(ns - 1);
    float inv_nm1 = 1.0f / nm1;

    float uf = (float)u, vf = (float)v;

    // tgt_cam = (k_inv @ [u,v,1]) * sdd
    float tcx = (k_inv[0]*uf + k_inv[1]*vf + k_inv[2]) * sdd;
    float tcy = (k_inv[3]*uf + k_inv[4]*vf + k_inv[5]) * sdd;
    float tcz = (k_inv[6]*uf + k_inv[7]*vf + k_inv[8]) * sdd;

    // R, t from rt_inv (4x4, row major)
    float tx = rt_inv[3], ty = rt_inv[7], tz = rt_inv[11];
    float tgx = rt_inv[0]*tcx + rt_inv[1]*tcy + rt_inv[2]*tcz + tx;
    float tgy = rt_inv[4]*tcx + rt_inv[5]*tcy + rt_inv[6]*tcz + ty;
    float tgz = rt_inv[8]*tcx + rt_inv[9]*tcy + rt_inv[10]*tcz + tz;

    // ray = tgt - src  (src = t)
    float rx = tgx - tx, ry = tgy - ty, rz = tgz - tz;

    float step = sqrtf(rx*rx + ry*ry + rz*rz) * inv_nm1;

    // affine rows
    float a00 = aff[0], a01 = aff[1], a02 = aff[2],  b0 = aff[3];
    float a10 = aff[4], a11 = aff[5], a12 = aff[6],  b1 = aff[7];
    float a20 = aff[8], a21 = aff[9], a22 = aff[10], b2 = aff[11];

    // vox-space segment: vox(t) = c + t*d
    float cx = a00*tx + a01*ty + a02*tz + b0;
    float cy = a10*tx + a11*ty + a12*tz + b1;
    float cz = a20*tx + a21*ty + a22*tz + b2;
    float dx = a00*rx + a01*ry + a02*rz;
    float dy = a10*rx + a11*ry + a12*rz;
    float dz = a20*rx + a21*ry + a22*rz;

    // Slab-clip against [-1, VOLN]^3 (conservative; per-corner guards keep exactness)
    const float LO = -1.0f - 1e-3f;
    const float HI = (float)VOLN + 1e-3f;
    float tmin = 0.0f, tmax = 1.0f;
    {
        float c[3] = {cx, cy, cz};
        float d[3] = {dx, dy, dz};
        #pragma unroll
        for (int a = 0; a < 3; a++) {
            if (fabsf(d[a]) > 1e-8f) {
                float r  = 1.0f / d[a];
                float t0 = (LO - c[a]) * r;
                float t1 = (HI - c[a]) * r;
                float lo = fminf(t0, t1), hi = fmaxf(t0, t1);
                tmin = fmaxf(tmin, lo);
                tmax = fminf(tmax, hi);
            } else if (c[a] < LO || c[a] > HI) {
                tmin = 1.0f; tmax = 0.0f;  // empty
            }
        }
    }

    int s0 = 0, s1 = -1;
    if (tmax >= tmin) {
        s0 = (int)floorf(tmin * nm1);  if (s0 < 0) s0 = 0;
        s1 = (int)ceilf (tmax * nm1);  if (s1 > ns - 1) s1 = ns - 1;
    }

    float sum = 0.0f;

    // Each loop trip: the 32 lanes cover 32 CONSECUTIVE samples of this one
    // pixel's ray (~65 contiguous z-voxels, mostly one (ix,iy) row), so each
    // corner LDG touches ~2-3 cache lines warp-wide.
    for (int s = s0 + sub; s <= s1; s += SUBS) {
        float t = (float)s * inv_nm1;
        float x = fmaf(t, dx, cx);
        float y = fmaf(t, dy, cy);
        float z = fmaf(t, dz, cz);

        float fx = floorf(x), fy = floorf(y), fz = floorf(z);
        int ix = (int)fx, iy = (int)fy, iz = (int)fz;
        float wx = x - fx, wy = y - fy, wz = z - fz;

        float val;
        if (ix >= 0 && ix < VOLN - 1 &&
            iy >= 0 && iy < VOLN - 1 &&
            iz >= 0 && iz < VOLN - 1) {
            int base = (ix << 16) + (iy << 8) + iz;
            float v000 = vol[base];
            float v001 = vol[base + 1];
            float v010 = vol[base + 256];
            float v011 = vol[base + 257];
            float v100 = vol[base + 65536];
            float v101 = vol[base + 65537];
            float v110 = vol[base + 65536 + 256];
            float v111 = vol[base + 65536 + 257];
            float c00 = v000 + wz * (v001 - v000);
            float c01 = v010 + wz * (v011 - v010);
            float c10 = v100 + wz * (v101 - v100);
            float c11 = v110 + wz * (v111 - v110);
            float c0  = c00 + wy * (c01 - c00);
            float c1  = c10 + wy * (c11 - c10);
            val = c0 + wx * (c1 - c0);
        } else {
            bool x0 = ((unsigned)ix      < (unsigned)VOLN);
            bool x1 = ((unsigned)(ix+1)  < (unsigned)VOLN);
            bool y0 = ((unsigned)iy      < (unsigned)VOLN);
            bool y1 = ((unsigned)(iy+1)  < (unsigned)VOLN);
            bool z0 = ((unsigned)iz      < (unsigned)VOLN);
            bool z1 = ((unsigned)(iz+1)  < (unsigned)VOLN);
            if (!((x0|x1) && (y0|y1) && (z0|z1))) {
                val = 0.0f;
            } else {
                long base = (long)ix * 65536 + (long)iy * 256 + (long)iz;
                float v000 = (x0 && y0 && z0) ? vol[base]               : 0.0f;
                float v001 = (x0 && y0 && z1) ? vol[base + 1]           : 0.0f;
                float v010 = (x0 && y1 && z0) ? vol[base + 256]         : 0.0f;
                float v011 = (x0 && y1 && z1) ? vol[base + 257]         : 0.0f;
                float v100 = (x1 && y0 && z0) ? vol[base + 65536]       : 0.0f;
                float v101 = (x1 && y0 && z1) ? vol[base + 65537]       : 0.0f;
                float v110 = (x1 && y1 && z0) ? vol[base + 65536 + 256] : 0.0f;
                float v111 = (x1 && y1 && z1) ? vol[base + 65536 + 257] : 0.0f;
                float c00 = v000 + wz * (v001 - v000);
                float c01 = v010 + wz * (v011 - v010);
                float c10 = v100 + wz * (v101 - v100);
                float c11 = v110 + wz * (v111 - v110);
                float c0  = c00 + wy * (c01 - c00);
                float c1  = c10 + wy * (c11 - c10);
                val = c0 + wx * (c1 - c0);
            }
        }
        sum += val;
    }

    // full-warp tree reduction
    sum += __shfl_xor_sync(0xFFFFFFFFu, sum, 16);
    sum += __shfl_xor_sync(0xFFFFFFFFu, sum, 8);
    sum += __shfl_xor_sync(0xFFFFFFFFu, sum, 4);
    sum += __shfl_xor_sync(0xFFFFFFFFu, sum, 2);
    sum += __shfl_xor_sync(0xFFFFFFFFu, sum, 1);

    if (sub == 0) out[pix] = sum * step;
}

extern "C" void kernel_launch(void* const* d_in, const int* in_sizes, int n_in,
                              void* d_out, int out_size)
{
    const float* vol    = (const float*)d_in[0];
    const float* k_inv  = (const float*)d_in[1];
    const float* rt_inv = (const float*)d_in[2];
    const float* sdd    = (const float*)d_in[3];
    const float* aff    = (const float*)d_in[4];
    const int*   ns     = (const int*)  d_in[5];
    float* out = (float*)d_out;

    int total = H_IMG * W_IMG * SUBS;      // 1,280,000 threads
    int block = 256;
    int grid  = (total + block - 1) / block;
    drr_kernel<<<grid, block>>>(vol, k_inv, rt_inv, sdd, aff, ns, out);
}

// round 5
// speedup vs baseline: 1.2064x; 1.2064x over previous
#include <cuda_runtime.h>

#define H_IMG 200
#define W_IMG 200
#define VOLN  256
#define SUBS  16   // warp = 2 adjacent-u pixels x 16 consecutive samples

__global__ void __launch_bounds__(256) drr_kernel(
    const float* __restrict__ vol,
    const float* __restrict__ k_inv,    // (1,3,3)
    const float* __restrict__ rt_inv,   // (1,4,4)
    const float* __restrict__ sdd_p,    // (1,)
    const float* __restrict__ aff,      // (4,4)
    const int*   __restrict__ ns_p,     // scalar
    float* __restrict__ out)            // (H*W,)
{
    int gtid = blockIdx.x * blockDim.x + threadIdx.x;
    int pix  = gtid >> 4;            // / SUBS
    int sub  = gtid & (SUBS - 1);
    if (pix >= H_IMG * W_IMG) return;

    int u = pix % W_IMG;
    int v = pix / W_IMG;

    float sdd = sdd_p[0];
    int   ns  = ns_p[0];
    float nm1 = (float)(ns - 1);
    float inv_nm1 = 1.0f / nm1;

    float uf = (float)u, vf = (float)v;

    // tgt_cam = (k_inv @ [u,v,1]) * sdd
    float tcx = (k_inv[0]*uf + k_inv[1]*vf + k_inv[2]) * sdd;
    float tcy = (k_inv[3]*uf + k_inv[4]*vf + k_inv[5]) * sdd;
    float tcz = (k_inv[6]*uf + k_inv[7]*vf + k_inv[8]) * sdd;

    // R, t from rt_inv (4x4, row major)
    float tx = rt_inv[3], ty = rt_inv[7], tz = rt_inv[11];
    float tgx = rt_inv[0]*tcx + rt_inv[1]*tcy + rt_inv[2]*tcz + tx;
    float tgy = rt_inv[4]*tcx + rt_inv[5]*tcy + rt_inv[6]*tcz + ty;
    float tgz = rt_inv[8]*tcx + rt_inv[9]*tcy + rt_inv[10]*tcz + tz;

    // ray = tgt - src  (src = t)
    float rx = tgx - tx, ry = tgy - ty, rz = tgz - tz;

    float step = sqrtf(rx*rx + ry*ry + rz*rz) * inv_nm1;

    // affine rows
    float a00 = aff[0], a01 = aff[1], a02 = aff[2],  b0 = aff[3];
    float a10 = aff[4], a11 = aff[5], a12 = aff[6],  b1 = aff[7];
    float a20 = aff[8], a21 = aff[9], a22 = aff[10], b2 = aff[11];

    // vox-space segment: vox(t) = c + t*d
    float cx = a00*tx + a01*ty + a02*tz + b0;
    float cy = a10*tx + a11*ty + a12*tz + b1;
    float cz = a20*tx + a21*ty + a22*tz + b2;
    float dx = a00*rx + a01*ry + a02*rz;
    float dy = a10*rx + a11*ry + a12*rz;
    float dz = a20*rx + a21*ry + a22*rz;

    // Slab-clip against [-1, VOLN]^3 (conservative; per-corner guards keep exactness)
    const float LO = -1.0f - 1e-3f;
    const float HI = (float)VOLN + 1e-3f;
    float tmin = 0.0f, tmax = 1.0f;
    {
        float c[3] = {cx, cy, cz};
        float d[3] = {dx, dy, dz};
        #pragma unroll
        for (int a = 0; a < 3; a++) {
            if (fabsf(d[a]) > 1e-8f) {
                float r  = 1.0f / d[a];
                float t0 = (LO - c[a]) * r;
                float t1 = (HI - c[a]) * r;
                float lo = fminf(t0, t1), hi = fmaxf(t0, t1);
                tmin = fmaxf(tmin, lo);
                tmax = fminf(tmax, hi);
            } else if (c[a] < LO || c[a] > HI) {
                tmin = 1.0f; tmax = 0.0f;  // empty
            }
        }
    }

    int s0 = 0, s1 = -1;
    if (tmax >= tmin) {
        s0 = (int)floorf(tmin * nm1);  if (s0 < 0) s0 = 0;
        s1 = (int)ceilf (tmax * nm1);  if (s1 > ns - 1) s1 = ns - 1;
    }

    float sum = 0.0f;

    // 16 lanes = 16 CONSECUTIVE samples per pixel per trip.  iz advances by
    // ~2.044/sample, so parity is warp-uniform except ~1 flip per 23 samples
    // -> the float2 fast path below is nearly divergence-free.
    for (int s = s0 + sub; s <= s1; s += SUBS) {
        float t = (float)s * inv_nm1;
        float x = fmaf(t, dx, cx);
        float y = fmaf(t, dy, cy);
        float z = fmaf(t, dz, cz);

        float fx = floorf(x), fy = floorf(y), fz = floorf(z);
        int ix = (int)fx, iy = (int)fy, iz = (int)fz;
        float wx = x - fx, wy = y - fy, wz = z - fz;

        float val;
        if (ix >= 0 && ix < VOLN - 1 &&
            iy >= 0 && iy < VOLN - 1 &&
            iz >= 0 && iz < VOLN - 1) {
            int base = (ix << 16) + (iy << 8) + iz;
            float v000, v001, v010, v011, v100, v101, v110, v111;
            if ((iz & 1) == 0) {
                // aligned z-pairs: 4x LDG.64, same cache lines as 8x LDG.32
                float2 e00 = *(const float2*)(vol + base);
                float2 e01 = *(const float2*)(vol + base + 256);
                float2 e10 = *(const float2*)(vol + base + 65536);
                float2 e11 = *(const float2*)(vol + base + 65536 + 256);
                v000 = e00.x; v001 = e00.y;
                v010 = e01.x; v011 = e01.y;
                v100 = e10.x; v101 = e10.y;
                v110 = e11.x; v111 = e11.y;
            } else {
                v000 = vol[base];
                v001 = vol[base + 1];
                v010 = vol[base + 256];
                v011 = vol[base + 257];
                v100 = vol[base + 65536];
                v101 = vol[base + 65537];
                v110 = vol[base + 65536 + 256];
                v111 = vol[base + 65536 + 257];
            }
            float c00 = v000 + wz * (v001 - v000);
            float c01 = v010 + wz * (v011 - v010);
            float c10 = v100 + wz * (v101 - v100);
            float c11 = v110 + wz * (v111 - v110);
            float c0  = c00 + wy * (c01 - c00);
            float c1  = c10 + wy * (c11 - c10);
            val = c0 + wx * (c1 - c0);
        } else {
            bool x0 = ((unsigned)ix      < (unsigned)VOLN);
            bool x1 = ((unsigned)(ix+1)  < (unsigned)VOLN);
            bool y0 = ((unsigned)iy      < (unsigned)VOLN);
            bool y1 = ((unsigned)(iy+1)  < (unsigned)VOLN);
            bool z0 = ((unsigned)iz      < (unsigned)VOLN);
            bool z1 = ((unsigned)(iz+1)  < (unsigned)VOLN);
            if (!((x0|x1) && (y0|y1) && (z0|z1))) {
                val = 0.0f;
            } else {
                long base = (long)ix * 65536 + (long)iy * 256 + (long)iz;
                float v000 = (x0 && y0 && z0) ? vol[base]               : 0.0f;
                float v001 = (x0 && y0 && z1) ? vol[base + 1]           : 0.0f;
                float v010 = (x0 && y1 && z0) ? vol[base + 256]         : 0.0f;
                float v011 = (x0 && y1 && z1) ? vol[base + 257]         : 0.0f;
                float v100 = (x1 && y0 && z0) ? vol[base + 65536]       : 0.0f;
                float v101 = (x1 && y0 && z1) ? vol[base + 65537]       : 0.0f;
                float v110 = (x1 && y1 && z0) ? vol[base + 65536 + 256] : 0.0f;
                float v111 = (x1 && y1 && z1) ? vol[base + 65536 + 257] : 0.0f;
                float c00 = v000 + wz * (v001 - v000);
                float c01 = v010 + wz * (v011 - v010);
                float c10 = v100 + wz * (v101 - v100);
                float c11 = v110 + wz * (v111 - v110);
                float c0  = c00 + wy * (c01 - c00);
                float c1  = c10 + wy * (c11 - c10);
                val = c0 + wx * (c1 - c0);
            }
        }
        sum += val;
    }

    // tree-reduce within the 16-lane pixel group
    sum += __shfl_xor_sync(0xFFFFFFFFu, sum, 8, SUBS);
    sum += __shfl_xor_sync(0xFFFFFFFFu, sum, 4, SUBS);
    sum += __shfl_xor_sync(0xFFFFFFFFu, sum, 2, SUBS);
    sum += __shfl_xor_sync(0xFFFFFFFFu, sum, 1, SUBS);

    if (sub == 0) out[pix] = sum * step;
}

extern "C" void kernel_launch(void* const* d_in, const int* in_sizes, int n_in,
                              void* d_out, int out_size)
{
    const float* vol    = (const float*)d_in[0];
    const float* k_inv  = (const float*)d_in[1];
    const float* rt_inv = (const float*)d_in[2];
    const float* sdd    = (const float*)d_in[3];
    const float* aff    = (const float*)d_in[4];
    const int*   ns     = (const int*)  d_in[5];
    float* out = (float*)d_out;

    int total = H_IMG * W_IMG * SUBS;      // 640,000 threads
    int block = 256;
    int grid  = (total + block - 1) / block;
    drr_kernel<<<grid, block>>>(vol, k_inv, rt_inv, sdd, aff, ns, out);
}